// round 1
// baseline (speedup 1.0000x reference)
#include <cuda_runtime.h>
#include <math.h>
#include <stdint.h>

// ---------------------------------------------------------------------------
// Problem dims
// ---------------------------------------------------------------------------
constexpr int BATCH = 4;
constexpr int SEQ   = 1024;
constexpr int CDIM  = 2048;
constexpr int NHEAD = 16;
constexpr int HS    = 128;
constexpr int NLQ   = 512;
constexpr int NLKV  = 512;
constexpr int DHR   = 64;
constexpr int QKDIM = NLKV + DHR;   // 576 = concat(c-path, rope-path)

// ---------------------------------------------------------------------------
// Scratch (static device arrays; no allocation allowed)
// ---------------------------------------------------------------------------
__device__ float g_cq  [(size_t)BATCH * SEQ * NLQ];            //  8 MB
__device__ float g_cqr [(size_t)BATCH * SEQ * NHEAD * DHR];    // 16 MB
__device__ float g_ckr [(size_t)BATCH * SEQ * DHR];            //  1 MB
__device__ float g_KC  [(size_t)BATCH * SEQ * QKDIM];          //  9 MB  [c_kv | k_r]
__device__ float g_QC  [(size_t)BATCH * NHEAD * SEQ * QKDIM];  // 151 MB [q_abs | q_r]
__device__ float g_keff[(size_t)NHEAD * NLQ * NLKV];           // 17 MB
__device__ float g_Z   [(size_t)CDIM * NLKV];                  //  4 MB  Z = W_o @ W_uv
__device__ float g_S   [(size_t)BATCH * NHEAD * SEQ * SEQ];    // 268 MB logits/probs
__device__ float g_O   [(size_t)BATCH * NHEAD * SEQ * NLKV];   // 134 MB

// ---------------------------------------------------------------------------
// Generic batched SGEMM:  C[z] = A[z] @ op(B[z])
//   z0 = z / zdiv, z1 = z % zdiv;  X += z0*sX0 + z1*sX1
//   TB=false: B is KxN (ld=ldb);  TB=true: B is NxK (compute A @ B^T)
// Tile: 128x128x8, 256 threads, 8x8 per thread. Bounds-checked.
// ---------------------------------------------------------------------------
constexpr int BM = 128, BN = 128, BK = 8, TM = 8, TN = 8;

template <bool TB>
__global__ __launch_bounds__(256)
void sgemm(const float* __restrict__ A, long long sA0, long long sA1, int lda,
           const float* __restrict__ Bm, long long sB0, long long sB1, int ldb,
           float* __restrict__ Cm, long long sC0, long long sC1, int ldc,
           int M, int N, int K, int zdiv)
{
    const int z  = blockIdx.z;
    const int z0 = z / zdiv, z1 = z % zdiv;
    A  += z0 * sA0 + z1 * sA1;
    Bm += z0 * sB0 + z1 * sB1;
    Cm += z0 * sC0 + z1 * sC1;

    const int m0 = blockIdx.y * BM;
    const int n0 = blockIdx.x * BN;

    __shared__ float As[BK][BM + 1];
    __shared__ float Bs[BK][BN + 1];

    const int tid = threadIdx.x;
    const int tx  = tid % 16, ty = tid / 16;
    const int tm  = ty * TM, tn = tx * TN;

    float acc[TM][TN] = {};

    for (int k0 = 0; k0 < K; k0 += BK) {
        // load A tile (BM x BK)
#pragma unroll
        for (int i = 0; i < 4; i++) {
            int idx = tid + i * 256;            // 0..1023
            int m = idx >> 3, k = idx & 7;
            float v = 0.f;
            if (m0 + m < M && k0 + k < K)
                v = A[(long long)(m0 + m) * lda + (k0 + k)];
            As[k][m] = v;
        }
        // load B tile (BK x BN)
#pragma unroll
        for (int i = 0; i < 4; i++) {
            int idx = tid + i * 256;
            float v = 0.f;
            if (TB) {
                int n = idx >> 3, k = idx & 7;
                if (n0 + n < N && k0 + k < K)
                    v = Bm[(long long)(n0 + n) * ldb + (k0 + k)];
                Bs[k][n] = v;
            } else {
                int k = idx >> 7, n = idx & 127;
                if (k0 + k < K && n0 + n < N)
                    v = Bm[(long long)(k0 + k) * ldb + (n0 + n)];
                Bs[k][n] = v;
            }
        }
        __syncthreads();

#pragma unroll
        for (int k = 0; k < BK; k++) {
            float a[TM], b[TN];
#pragma unroll
            for (int i = 0; i < TM; i++) a[i] = As[k][tm + i];
#pragma unroll
            for (int j = 0; j < TN; j++) b[j] = Bs[k][tn + j];
#pragma unroll
            for (int i = 0; i < TM; i++)
#pragma unroll
                for (int j = 0; j < TN; j++)
                    acc[i][j] += a[i] * b[j];
        }
        __syncthreads();
    }

#pragma unroll
    for (int i = 0; i < TM; i++) {
        int m = m0 + tm + i;
        if (m >= M) break;
#pragma unroll
        for (int j = 0; j < TN; j++) {
            int n = n0 + tn + j;
            if (n < N) Cm[(long long)m * ldc + n] = acc[i][j];
        }
    }
}

// ---------------------------------------------------------------------------
// RoPE: q_r path.  c_qr layout: [b*T + t][h*64 + 2j(+1)]  ->  QC[b,h,t][512+2j(+1)]
// ---------------------------------------------------------------------------
__global__ void rope_q_kernel(const float* __restrict__ cqr,
                              const float* __restrict__ fc,
                              const float* __restrict__ fs,
                              float* __restrict__ QC)
{
    int idx = blockIdx.x * 256 + threadIdx.x;          // BATCH*SEQ*NHEAD*32
    if (idx >= BATCH * SEQ * NHEAD * 32) return;
    int j  = idx & 31;
    int h  = (idx >> 5) & 15;
    int bt = idx >> 9;
    int t  = bt & (SEQ - 1);
    int b  = bt >> 10;

    long long src = (long long)bt * (NHEAD * DHR) + h * DHR + 2 * j;
    float re = cqr[src], im = cqr[src + 1];
    float c = fc[t * 32 + j], s = fs[t * 32 + j];

    long long row = ((long long)(b * NHEAD + h) * SEQ + t);
    QC[row * QKDIM + NLKV + 2 * j]     = re * c - im * s;
    QC[row * QKDIM + NLKV + 2 * j + 1] = re * s + im * c;
}

// RoPE: k_r path. c_kr layout: [b*T+t][2j(+1)] -> KC[b*T+t][512+2j(+1)]
__global__ void rope_k_kernel(const float* __restrict__ ckr,
                              const float* __restrict__ fc,
                              const float* __restrict__ fs,
                              float* __restrict__ KC)
{
    int idx = blockIdx.x * 256 + threadIdx.x;          // BATCH*SEQ*32
    if (idx >= BATCH * SEQ * 32) return;
    int j  = idx & 31;
    int bt = idx >> 5;
    int t  = bt & (SEQ - 1);

    long long src = (long long)bt * DHR + 2 * j;
    float re = ckr[src], im = ckr[src + 1];
    float c = fc[t * 32 + j], s = fs[t * 32 + j];

    KC[(long long)bt * QKDIM + NLKV + 2 * j]     = re * c - im * s;
    KC[(long long)bt * QKDIM + NLKV + 2 * j + 1] = re * s + im * c;
}

// ---------------------------------------------------------------------------
// Causal softmax over S rows. One block (256 thr) per (b,h,t) row of length T.
// Applies scale, masks s > t (set 0 after softmax).
// ---------------------------------------------------------------------------
__global__ void softmax_kernel(float* __restrict__ S)
{
    const float scale = 0.07216878364870322f;  // 1/sqrt(HS+DHR)=1/sqrt(192)
    long long r = blockIdx.x;                  // 0 .. B*NH*T-1
    int t = (int)(r & (SEQ - 1));
    float* row = S + r * SEQ;
    int n = t + 1;
    int tid = threadIdx.x;
    __shared__ float red[256];

    float m = -1e30f;
    for (int i = tid; i < n; i += 256) m = fmaxf(m, row[i]);
    red[tid] = m; __syncthreads();
    for (int s = 128; s > 0; s >>= 1) {
        if (tid < s) red[tid] = fmaxf(red[tid], red[tid + s]);
        __syncthreads();
    }
    m = red[0] * scale;
    __syncthreads();

    float sum = 0.f;
    for (int i = tid; i < n; i += 256) {
        float e = __expf(row[i] * scale - m);
        row[i] = e;
        sum += e;
    }
    red[tid] = sum; __syncthreads();
    for (int s = 128; s > 0; s >>= 1) {
        if (tid < s) red[tid] += red[tid + s];
        __syncthreads();
    }
    float inv = 1.0f / red[0];
    __syncthreads();

    for (int i = tid; i < n; i += 256) row[i] *= inv;
    for (int i = n + tid; i < SEQ; i += 256) row[i] = 0.f;
}

// ---------------------------------------------------------------------------
// Launch
// ---------------------------------------------------------------------------
extern "C" void kernel_launch(void* const* d_in, const int* in_sizes, int n_in,
                              void* d_out, int out_size)
{
    const float* x     = (const float*)d_in[0];
    const float* W_dq  = (const float*)d_in[1];
    const float* W_uq  = (const float*)d_in[2];
    const float* W_dkv = (const float*)d_in[3];
    const float* W_uk  = (const float*)d_in[4];
    const float* W_uv  = (const float*)d_in[5];
    const float* W_o   = (const float*)d_in[6];
    const float* W_qr  = (const float*)d_in[7];
    const float* W_kr  = (const float*)d_in[8];
    const float* fc    = (const float*)d_in[9];
    const float* fs    = (const float*)d_in[10];
    float* out = (float*)d_out;

    float *cq, *cqr, *ckr, *KC, *QC, *keff, *Z, *S, *O;
    cudaGetSymbolAddress((void**)&cq,   g_cq);
    cudaGetSymbolAddress((void**)&cqr,  g_cqr);
    cudaGetSymbolAddress((void**)&ckr,  g_ckr);
    cudaGetSymbolAddress((void**)&KC,   g_KC);
    cudaGetSymbolAddress((void**)&QC,   g_QC);
    cudaGetSymbolAddress((void**)&keff, g_keff);
    cudaGetSymbolAddress((void**)&Z,    g_Z);
    cudaGetSymbolAddress((void**)&S,    g_S);
    cudaGetSymbolAddress((void**)&O,    g_O);

    const long long BT = (long long)BATCH * SEQ;   // 4096

    // 1. Z = W_o @ W_uv               (2048 x 512 x K=2048)
    sgemm<false><<<dim3(NLKV / BN, CDIM / BM, 1), 256>>>(
        W_o, 0, 0, CDIM,  W_uv, 0, 0, NLKV,  Z, 0, 0, NLKV,
        CDIM, NLKV, CDIM, 1);

    // 2. k_eff[h] = W_uq_h (512x128) @ W_uk_h (128x512)
    sgemm<false><<<dim3(NLKV / BN, NLQ / BM, NHEAD), 256>>>(
        W_uq, 0, HS, CDIM,
        W_uk, 0, (long long)HS * NLKV, NLKV,
        keff, 0, (long long)NLQ * NLKV, NLKV,
        NLQ, NLKV, HS, NHEAD);

    // 3. c_q = x @ W_dq^T             (4096 x 512 x K=2048)
    sgemm<true><<<dim3(NLQ / BN, BT / BM, 1), 256>>>(
        x, 0, 0, CDIM,  W_dq, 0, 0, CDIM,  cq, 0, 0, NLQ,
        (int)BT, NLQ, CDIM, 1);

    // 4. c_kv = x @ W_dkv^T -> KC[:, 0:512]
    sgemm<true><<<dim3(NLKV / BN, BT / BM, 1), 256>>>(
        x, 0, 0, CDIM,  W_dkv, 0, 0, CDIM,  KC, 0, 0, QKDIM,
        (int)BT, NLKV, CDIM, 1);

    // 5. c_kr = x @ W_kr^T            (4096 x 64 x 2048)
    sgemm<true><<<dim3(1, BT / BM, 1), 256>>>(
        x, 0, 0, CDIM,  W_kr, 0, 0, CDIM,  ckr, 0, 0, DHR,
        (int)BT, DHR, CDIM, 1);

    // 6. c_qr = c_q @ W_qr^T          (4096 x 1024 x 512)
    sgemm<true><<<dim3((NHEAD * DHR) / BN, BT / BM, 1), 256>>>(
        cq, 0, 0, NLQ,  W_qr, 0, 0, NLQ,  cqr, 0, 0, NHEAD * DHR,
        (int)BT, NHEAD * DHR, NLQ, 1);

    // 7. RoPE into QC / KC tails
    rope_q_kernel<<<(BATCH * SEQ * NHEAD * 32 + 255) / 256, 256>>>(cqr, fc, fs, QC);
    rope_k_kernel<<<(BATCH * SEQ * 32 + 255) / 256, 256>>>(ckr, fc, fs, KC);

    // 8. q_abs[b,h] = c_q[b] @ k_eff[h] -> QC[b,h][:, 0:512]
    sgemm<false><<<dim3(NLKV / BN, SEQ / BM, BATCH * NHEAD), 256>>>(
        cq, (long long)SEQ * NLQ, 0, NLQ,
        keff, 0, (long long)NLQ * NLKV, NLKV,
        QC, (long long)NHEAD * SEQ * QKDIM, (long long)SEQ * QKDIM, QKDIM,
        SEQ, NLKV, NLQ, NHEAD);

    // 9. S[b,h] = QC[b,h] @ KC[b]^T    (1024 x 1024 x K=576)
    sgemm<true><<<dim3(SEQ / BN, SEQ / BM, BATCH * NHEAD), 256>>>(
        QC, (long long)NHEAD * SEQ * QKDIM, (long long)SEQ * QKDIM, QKDIM,
        KC, (long long)SEQ * QKDIM, 0, QKDIM,
        S, (long long)NHEAD * SEQ * SEQ, (long long)SEQ * SEQ, SEQ,
        SEQ, SEQ, QKDIM, NHEAD);

    // 10. causal softmax (in place)
    softmax_kernel<<<BATCH * NHEAD * SEQ, 256>>>(S);

    // 11. O[b,h] = P[b,h] @ c_kv[b]    (1024 x 512 x K=1024), c_kv in KC (ld 576)
    sgemm<false><<<dim3(NLKV / BN, SEQ / BM, BATCH * NHEAD), 256>>>(
        S, (long long)NHEAD * SEQ * SEQ, (long long)SEQ * SEQ, SEQ,
        KC, (long long)SEQ * QKDIM, 0, QKDIM,
        O, (long long)NHEAD * SEQ * NLKV, (long long)SEQ * NLKV, NLKV,
        SEQ, NLKV, SEQ, NHEAD);

    // 12. out[b][:, h*128:(h+1)*128] = O[b,h] @ Z[h*128:(h+1)*128, :]^T
    sgemm<true><<<dim3(1, SEQ / BM, BATCH * NHEAD), 256>>>(
        O, (long long)NHEAD * SEQ * NLKV, (long long)SEQ * NLKV, NLKV,
        Z, 0, (long long)HS * NLKV, NLKV,
        out, (long long)SEQ * CDIM, HS, CDIM,
        SEQ, HS, NLKV, NHEAD);
}

// round 2
// speedup vs baseline: 1.0008x; 1.0008x over previous
#include <cuda_runtime.h>
#include <math.h>
#include <stdint.h>

// ---------------------------------------------------------------------------
// Problem dims
// ---------------------------------------------------------------------------
constexpr int BATCH = 4;
constexpr int SEQ   = 1024;
constexpr int CDIM  = 2048;
constexpr int NHEAD = 16;
constexpr int HS    = 128;
constexpr int NLQ   = 512;
constexpr int NLKV  = 512;
constexpr int DHR   = 64;
constexpr int QKDIM = NLKV + DHR;   // 576 = concat(c-path, rope-path)

// ---------------------------------------------------------------------------
// Scratch (static device arrays; no allocation allowed)
// ---------------------------------------------------------------------------
__device__ float g_cq  [(size_t)BATCH * SEQ * NLQ];            //  8 MB
__device__ float g_cqr [(size_t)BATCH * SEQ * NHEAD * DHR];    // 16 MB
__device__ float g_ckr [(size_t)BATCH * SEQ * DHR];            //  1 MB
__device__ float g_KC  [(size_t)BATCH * SEQ * QKDIM];          //  9 MB  [c_kv | k_r]
__device__ float g_QC  [(size_t)BATCH * NHEAD * SEQ * QKDIM];  // 151 MB [q_abs | q_r]
__device__ float g_keff[(size_t)NHEAD * NLQ * NLKV];           // 17 MB
__device__ float g_Z   [(size_t)CDIM * NLKV];                  //  4 MB  Z = W_o @ W_uv
__device__ float g_S   [(size_t)BATCH * NHEAD * SEQ * SEQ];    // 268 MB logits/probs
__device__ float g_O   [(size_t)BATCH * NHEAD * SEQ * NLKV];   // 134 MB

// ---------------------------------------------------------------------------
// Generic batched SGEMM:  C[z] = A[z] @ op(B[z])
//   z0 = z / zdiv, z1 = z % zdiv;  X += z0*sX0 + z1*sX1
//   TB=false: B is KxN (ld=ldb);  TB=true: B is NxK (compute A @ B^T)
// Tile: 128x128x8, 256 threads, 8x8 per thread. Bounds-checked.
// ---------------------------------------------------------------------------
constexpr int BM = 128, BN = 128, BK = 8, TM = 8, TN = 8;

template <bool TB>
__global__ __launch_bounds__(256)
void sgemm(const float* __restrict__ A, long long sA0, long long sA1, int lda,
           const float* __restrict__ Bm, long long sB0, long long sB1, int ldb,
           float* __restrict__ Cm, long long sC0, long long sC1, int ldc,
           int M, int N, int K, int zdiv)
{
    const int z  = blockIdx.z;
    const int z0 = z / zdiv, z1 = z % zdiv;
    A  += z0 * sA0 + z1 * sA1;
    Bm += z0 * sB0 + z1 * sB1;
    Cm += z0 * sC0 + z1 * sC1;

    const int m0 = blockIdx.y * BM;
    const int n0 = blockIdx.x * BN;

    __shared__ float As[BK][BM + 1];
    __shared__ float Bs[BK][BN + 1];

    const int tid = threadIdx.x;
    const int tx  = tid % 16, ty = tid / 16;
    const int tm  = ty * TM, tn = tx * TN;

    float acc[TM][TN] = {};

    for (int k0 = 0; k0 < K; k0 += BK) {
        // load A tile (BM x BK)
#pragma unroll
        for (int i = 0; i < 4; i++) {
            int idx = tid + i * 256;            // 0..1023
            int m = idx >> 3, k = idx & 7;
            float v = 0.f;
            if (m0 + m < M && k0 + k < K)
                v = A[(long long)(m0 + m) * lda + (k0 + k)];
            As[k][m] = v;
        }
        // load B tile (BK x BN)
#pragma unroll
        for (int i = 0; i < 4; i++) {
            int idx = tid + i * 256;
            float v = 0.f;
            if (TB) {
                int n = idx >> 3, k = idx & 7;
                if (n0 + n < N && k0 + k < K)
                    v = Bm[(long long)(n0 + n) * ldb + (k0 + k)];
                Bs[k][n] = v;
            } else {
                int k = idx >> 7, n = idx & 127;
                if (k0 + k < K && n0 + n < N)
                    v = Bm[(long long)(k0 + k) * ldb + (n0 + n)];
                Bs[k][n] = v;
            }
        }
        __syncthreads();

#pragma unroll
        for (int k = 0; k < BK; k++) {
            float a[TM], b[TN];
#pragma unroll
            for (int i = 0; i < TM; i++) a[i] = As[k][tm + i];
#pragma unroll
            for (int j = 0; j < TN; j++) b[j] = Bs[k][tn + j];
#pragma unroll
            for (int i = 0; i < TM; i++)
#pragma unroll
                for (int j = 0; j < TN; j++)
                    acc[i][j] += a[i] * b[j];
        }
        __syncthreads();
    }

#pragma unroll
    for (int i = 0; i < TM; i++) {
        int m = m0 + tm + i;
        if (m >= M) break;
#pragma unroll
        for (int j = 0; j < TN; j++) {
            int n = n0 + tn + j;
            if (n < N) Cm[(long long)m * ldc + n] = acc[i][j];
        }
    }
}

// ---------------------------------------------------------------------------
// RoPE: q_r path.  c_qr layout: [b*T + t][h*64 + 2j(+1)]  ->  QC[b,h,t][512+2j(+1)]
// ---------------------------------------------------------------------------
__global__ void rope_q_kernel(const float* __restrict__ cqr,
                              const float* __restrict__ fc,
                              const float* __restrict__ fs,
                              float* __restrict__ QC)
{
    int idx = blockIdx.x * 256 + threadIdx.x;          // BATCH*SEQ*NHEAD*32
    if (idx >= BATCH * SEQ * NHEAD * 32) return;
    int j  = idx & 31;
    int h  = (idx >> 5) & 15;
    int bt = idx >> 9;
    int t  = bt & (SEQ - 1);
    int b  = bt >> 10;

    long long src = (long long)bt * (NHEAD * DHR) + h * DHR + 2 * j;
    float re = cqr[src], im = cqr[src + 1];
    float c = fc[t * 32 + j], s = fs[t * 32 + j];

    long long row = ((long long)(b * NHEAD + h) * SEQ + t);
    QC[row * QKDIM + NLKV + 2 * j]     = re * c - im * s;
    QC[row * QKDIM + NLKV + 2 * j + 1] = re * s + im * c;
}

// RoPE: k_r path. c_kr layout: [b*T+t][2j(+1)] -> KC[b*T+t][512+2j(+1)]
__global__ void rope_k_kernel(const float* __restrict__ ckr,
                              const float* __restrict__ fc,
                              const float* __restrict__ fs,
                              float* __restrict__ KC)
{
    int idx = blockIdx.x * 256 + threadIdx.x;          // BATCH*SEQ*32
    if (idx >= BATCH * SEQ * 32) return;
    int j  = idx & 31;
    int bt = idx >> 5;
    int t  = bt & (SEQ - 1);

    long long src = (long long)bt * DHR + 2 * j;
    float re = ckr[src], im = ckr[src + 1];
    float c = fc[t * 32 + j], s = fs[t * 32 + j];

    KC[(long long)bt * QKDIM + NLKV + 2 * j]     = re * c - im * s;
    KC[(long long)bt * QKDIM + NLKV + 2 * j + 1] = re * s + im * c;
}

// ---------------------------------------------------------------------------
// Causal softmax over S rows. One block (256 thr) per (b,h,t) row of length T.
// Applies scale, masks s > t (set 0 after softmax).
// ---------------------------------------------------------------------------
__global__ void softmax_kernel(float* __restrict__ S)
{
    const float scale = 0.07216878364870322f;  // 1/sqrt(HS+DHR)=1/sqrt(192)
    long long r = blockIdx.x;                  // 0 .. B*NH*T-1
    int t = (int)(r & (SEQ - 1));
    float* row = S + r * SEQ;
    int n = t + 1;
    int tid = threadIdx.x;
    __shared__ float red[256];

    float m = -1e30f;
    for (int i = tid; i < n; i += 256) m = fmaxf(m, row[i]);
    red[tid] = m; __syncthreads();
    for (int s = 128; s > 0; s >>= 1) {
        if (tid < s) red[tid] = fmaxf(red[tid], red[tid + s]);
        __syncthreads();
    }
    m = red[0] * scale;
    __syncthreads();

    float sum = 0.f;
    for (int i = tid; i < n; i += 256) {
        float e = __expf(row[i] * scale - m);
        row[i] = e;
        sum += e;
    }
    red[tid] = sum; __syncthreads();
    for (int s = 128; s > 0; s >>= 1) {
        if (tid < s) red[tid] += red[tid + s];
        __syncthreads();
    }
    float inv = 1.0f / red[0];
    __syncthreads();

    for (int i = tid; i < n; i += 256) row[i] *= inv;
    for (int i = n + tid; i < SEQ; i += 256) row[i] = 0.f;
}

// ---------------------------------------------------------------------------
// Launch
// ---------------------------------------------------------------------------
extern "C" void kernel_launch(void* const* d_in, const int* in_sizes, int n_in,
                              void* d_out, int out_size)
{
    const float* x     = (const float*)d_in[0];
    const float* W_dq  = (const float*)d_in[1];
    const float* W_uq  = (const float*)d_in[2];
    const float* W_dkv = (const float*)d_in[3];
    const float* W_uk  = (const float*)d_in[4];
    const float* W_uv  = (const float*)d_in[5];
    const float* W_o   = (const float*)d_in[6];
    const float* W_qr  = (const float*)d_in[7];
    const float* W_kr  = (const float*)d_in[8];
    const float* fc    = (const float*)d_in[9];
    const float* fs    = (const float*)d_in[10];
    float* out = (float*)d_out;

    float *cq, *cqr, *ckr, *KC, *QC, *keff, *Z, *S, *O;
    cudaGetSymbolAddress((void**)&cq,   g_cq);
    cudaGetSymbolAddress((void**)&cqr,  g_cqr);
    cudaGetSymbolAddress((void**)&ckr,  g_ckr);
    cudaGetSymbolAddress((void**)&KC,   g_KC);
    cudaGetSymbolAddress((void**)&QC,   g_QC);
    cudaGetSymbolAddress((void**)&keff, g_keff);
    cudaGetSymbolAddress((void**)&Z,    g_Z);
    cudaGetSymbolAddress((void**)&S,    g_S);
    cudaGetSymbolAddress((void**)&O,    g_O);

    const long long BT = (long long)BATCH * SEQ;   // 4096

    // 1. Z = W_o @ W_uv               (2048 x 512 x K=2048)
    sgemm<false><<<dim3(NLKV / BN, CDIM / BM, 1), 256>>>(
        W_o, 0, 0, CDIM,  W_uv, 0, 0, NLKV,  Z, 0, 0, NLKV,
        CDIM, NLKV, CDIM, 1);

    // 2. k_eff[h] = W_uq_h (512x128) @ W_uk_h (128x512)
    sgemm<false><<<dim3(NLKV / BN, NLQ / BM, NHEAD), 256>>>(
        W_uq, 0, HS, CDIM,
        W_uk, 0, (long long)HS * NLKV, NLKV,
        keff, 0, (long long)NLQ * NLKV, NLKV,
        NLQ, NLKV, HS, NHEAD);

    // 3. c_q = x @ W_dq^T             (4096 x 512 x K=2048)
    sgemm<true><<<dim3(NLQ / BN, BT / BM, 1), 256>>>(
        x, 0, 0, CDIM,  W_dq, 0, 0, CDIM,  cq, 0, 0, NLQ,
        (int)BT, NLQ, CDIM, 1);

    // 4. c_kv = x @ W_dkv^T -> KC[:, 0:512]
    sgemm<true><<<dim3(NLKV / BN, BT / BM, 1), 256>>>(
        x, 0, 0, CDIM,  W_dkv, 0, 0, CDIM,  KC, 0, 0, QKDIM,
        (int)BT, NLKV, CDIM, 1);

    // 5. c_kr = x @ W_kr^T            (4096 x 64 x 2048)
    sgemm<true><<<dim3(1, BT / BM, 1), 256>>>(
        x, 0, 0, CDIM,  W_kr, 0, 0, CDIM,  ckr, 0, 0, DHR,
        (int)BT, DHR, CDIM, 1);

    // 6. c_qr = c_q @ W_qr^T          (4096 x 1024 x 512)
    sgemm<true><<<dim3((NHEAD * DHR) / BN, BT / BM, 1), 256>>>(
        cq, 0, 0, NLQ,  W_qr, 0, 0, NLQ,  cqr, 0, 0, NHEAD * DHR,
        (int)BT, NHEAD * DHR, NLQ, 1);

    // 7. RoPE into QC / KC tails
    rope_q_kernel<<<(BATCH * SEQ * NHEAD * 32 + 255) / 256, 256>>>(cqr, fc, fs, QC);
    rope_k_kernel<<<(BATCH * SEQ * 32 + 255) / 256, 256>>>(ckr, fc, fs, KC);

    // 8. q_abs[b,h] = c_q[b] @ k_eff[h] -> QC[b,h][:, 0:512]
    sgemm<false><<<dim3(NLKV / BN, SEQ / BM, BATCH * NHEAD), 256>>>(
        cq, (long long)SEQ * NLQ, 0, NLQ,
        keff, 0, (long long)NLQ * NLKV, NLKV,
        QC, (long long)NHEAD * SEQ * QKDIM, (long long)SEQ * QKDIM, QKDIM,
        SEQ, NLKV, NLQ, NHEAD);

    // 9. S[b,h] = QC[b,h] @ KC[b]^T    (1024 x 1024 x K=576)
    sgemm<true><<<dim3(SEQ / BN, SEQ / BM, BATCH * NHEAD), 256>>>(
        QC, (long long)NHEAD * SEQ * QKDIM, (long long)SEQ * QKDIM, QKDIM,
        KC, (long long)SEQ * QKDIM, 0, QKDIM,
        S, (long long)NHEAD * SEQ * SEQ, (long long)SEQ * SEQ, SEQ,
        SEQ, SEQ, QKDIM, NHEAD);

    // 10. causal softmax (in place)
    softmax_kernel<<<BATCH * NHEAD * SEQ, 256>>>(S);

    // 11. O[b,h] = P[b,h] @ c_kv[b]    (1024 x 512 x K=1024), c_kv in KC (ld 576)
    sgemm<false><<<dim3(NLKV / BN, SEQ / BM, BATCH * NHEAD), 256>>>(
        S, (long long)NHEAD * SEQ * SEQ, (long long)SEQ * SEQ, SEQ,
        KC, (long long)SEQ * QKDIM, 0, QKDIM,
        O, (long long)NHEAD * SEQ * NLKV, (long long)SEQ * NLKV, NLKV,
        SEQ, NLKV, SEQ, NHEAD);

    // 12. out[b][:, h*128:(h+1)*128] = O[b,h] @ Z[h*128:(h+1)*128, :]^T
    sgemm<true><<<dim3(1, SEQ / BM, BATCH * NHEAD), 256>>>(
        O, (long long)NHEAD * SEQ * NLKV, (long long)SEQ * NLKV, NLKV,
        Z, 0, (long long)HS * NLKV, NLKV,
        out, (long long)SEQ * CDIM, HS, CDIM,
        SEQ, HS, NLKV, NHEAD);
}

// round 4
// speedup vs baseline: 6.0001x; 5.9955x over previous
#include <cuda_runtime.h>
#include <cuda_bf16.h>
#include <stdint.h>
#include <math.h>

using bf16 = __nv_bfloat16;

constexpr int BATCH = 4, SEQ = 1024, CDIM = 2048, NHEAD = 16, HS = 128;
constexpr int NLQ = 512, NLKV = 512, DHR = 64, QKDIM = 576;

// ---- scratch (hi/lo bf16 split pairs) ----
__device__ __align__(128) bf16 g_x_h[8388608],   g_x_l[8388608];
__device__ __align__(128) bf16 g_Wdq_h[1048576], g_Wdq_l[1048576];
__device__ __align__(128) bf16 g_Wdkv_h[1048576],g_Wdkv_l[1048576];
__device__ __align__(128) bf16 g_Wkr_h[131072],  g_Wkr_l[131072];
__device__ __align__(128) bf16 g_Wqr_h[524288],  g_Wqr_l[524288];
__device__ __align__(128) bf16 g_Wuq_h[1048576], g_Wuq_l[1048576];
__device__ __align__(128) bf16 g_Wo_h[4194304],  g_Wo_l[4194304];
__device__ __align__(128) bf16 g_WuvT_h[1048576],g_WuvT_l[1048576];
__device__ __align__(128) bf16 g_WukT_h[1048576],g_WukT_l[1048576];
__device__ __align__(128) bf16 g_Z_h[1048576],   g_Z_l[1048576];
__device__ __align__(128) bf16 g_keffT_h[4194304],g_keffT_l[4194304];
__device__ __align__(128) bf16 g_cq_h[2097152],  g_cq_l[2097152];
__device__ __align__(128) bf16 g_KC_h[2359296],  g_KC_l[2359296];
__device__ __align__(128) bf16 g_QC_h[37748736], g_QC_l[37748736];
__device__ __align__(128) bf16 g_P_h[67108864],  g_P_l[67108864];
__device__ __align__(128) bf16 g_O_h[33554432],  g_O_l[33554432];
__device__ __align__(128) bf16 g_ckvT_h[2097152],g_ckvT_l[2097152];
__device__ __align__(128) float g_cqr[4194304], g_ckr[262144], g_S[67108864];

// ---- helpers ----
__device__ __forceinline__ void split2(float v, bf16& h, bf16& l) {
    h = __float2bfloat16(v);
    l = __float2bfloat16(v - __bfloat162float(h));
}
__device__ __forceinline__ void ldsm4(uint32_t* r, uint32_t addr) {
    asm volatile("ldmatrix.sync.aligned.m8n8.x4.shared.b16 {%0,%1,%2,%3}, [%4];"
        : "=r"(r[0]), "=r"(r[1]), "=r"(r[2]), "=r"(r[3]) : "r"(addr));
}
__device__ __forceinline__ void mma16816(float* d, const uint32_t* a, const uint32_t* b) {
    asm volatile("mma.sync.aligned.m16n8k16.row.col.f32.bf16.bf16.f32 "
        "{%0,%1,%2,%3}, {%4,%5,%6,%7}, {%8,%9}, {%0,%1,%2,%3};"
        : "+f"(d[0]), "+f"(d[1]), "+f"(d[2]), "+f"(d[3])
        : "r"(a[0]), "r"(a[1]), "r"(a[2]), "r"(a[3]), "r"(b[0]), "r"(b[1]));
}
// swizzled smem address inside one 128x64bf16 (128B/row) tile
__device__ __forceinline__ uint32_t swz(uint32_t tile_base, int r, int kb16) {
    uint32_t byte = (uint32_t)(r * 128 + kb16 * 16);
    return tile_base + (byte ^ ((byte >> 3) & 0x70));
}

// ---- HMMA batched GEMM: D = (Ah+Al) @ (Bh+Bl)^T (3-term split) ----
// A: MxK (lda), B: NxK (ldb), both K-contiguous. Batch z: z0=z/zdiv, z1=z%zdiv.
// mode 0: fp32 C; mode 1: split Chi/Clo. causal 1: skip masked tiles; 2: clip K.
constexpr int BM = 128, BN = 128, BKC = 64;
constexpr int TILE_B = 16384;                 // one 128x64 bf16 tile
constexpr int BUF_B  = 4 * TILE_B;            // Ah, Al, Bh, Bl
constexpr int SMEM_GEMM = 2 * BUF_B;          // double buffered = 128 KB

__global__ __launch_bounds__(256, 1)
void gemm3(const bf16* __restrict__ Ah, const bf16* __restrict__ Al,
           long long sA0, long long sA1, int lda,
           const bf16* __restrict__ Bh, const bf16* __restrict__ Bl,
           long long sB0, long long sB1, int ldb,
           float* __restrict__ C, bf16* __restrict__ Chi, bf16* __restrict__ Clo,
           long long sC0, long long sC1, int ldc,
           int M, int N, int K, int zdiv, int mode, int causal)
{
    const int m0 = blockIdx.y * BM, n0 = blockIdx.x * BN;
    if (causal == 1 && n0 >= m0 + BM) return;
    const int z = blockIdx.z, z0 = z / zdiv, z1 = z % zdiv;
    Ah += z0*sA0 + z1*sA1;  Al += z0*sA0 + z1*sA1;
    Bh += z0*sB0 + z1*sB1;  Bl += z0*sB0 + z1*sB1;
    const long long coff = z0*sC0 + z1*sC1;

    extern __shared__ __align__(1024) char smem[];
    const uint32_t sb = (uint32_t)__cvta_generic_to_shared(smem);
    const int tid = threadIdx.x, wid = tid >> 5, lane = tid & 31;
    const int wm = (wid & 3) * 32;      // warp m-offset in tile
    const int wn = (wid >> 2) * 64;     // warp n-offset in tile

    const int Keff = (causal == 2) ? min(K, m0 + BM) : K;
    const int nch = Keff / BKC;

    // fill one chunk (4 tiles) into buffer `buf`
    auto fill = [&](int buf, int k0) {
        const uint32_t bb = sb + buf * BUF_B;
#pragma unroll
        for (int it = 0; it < 16; it++) {
            int idx = tid + it * 256;
            int tile = idx >> 10, r = (idx >> 3) & 127, c16 = idx & 7;
            uint32_t byte = (uint32_t)(r*128 + c16*16);
            uint32_t dst = bb + tile*TILE_B + (byte ^ ((byte >> 3) & 0x70));
            if (tile < 2) {
                const bf16* src = (tile == 0 ? Ah : Al) + (long long)(m0 + r)*lda + k0 + c16*8;
                asm volatile("cp.async.cg.shared.global [%0], [%1], 16;"::"r"(dst),"l"(src):"memory");
            } else if (n0 + r < N) {
                const bf16* src = (tile == 2 ? Bh : Bl) + (long long)(n0 + r)*ldb + k0 + c16*8;
                asm volatile("cp.async.cg.shared.global [%0], [%1], 16;"::"r"(dst),"l"(src):"memory");
            } else {
                asm volatile("st.shared.v4.b32 [%0], {%1,%1,%1,%1};"::"r"(dst),"r"(0u):"memory");
            }
        }
        asm volatile("cp.async.commit_group;" ::: "memory");
    };

    float acc[2][8][4];
#pragma unroll
    for (int i = 0; i < 2; i++)
#pragma unroll
        for (int j = 0; j < 8; j++)
#pragma unroll
            for (int q = 0; q < 4; q++) acc[i][j][q] = 0.f;

    fill(0, 0);
    for (int ci = 0; ci < nch; ci++) {
        if (ci + 1 < nch) {
            fill((ci + 1) & 1, (ci + 1) * BKC);
            asm volatile("cp.async.wait_group 1;" ::: "memory");
        } else {
            asm volatile("cp.async.wait_group 0;" ::: "memory");
        }
        __syncthreads();

        const uint32_t bb = sb + (ci & 1) * BUF_B;
        const uint32_t tAh = bb, tAl = bb + TILE_B, tBh = bb + 2*TILE_B, tBl = bb + 3*TILE_B;
        const int arow = wm + (lane & 15);
        const int brow = wn + (lane & 7) + ((lane >> 4) << 3);

#pragma unroll
        for (int ks = 0; ks < 4; ks++) {
            const int akb = ks*2 + (lane >> 4);
            const int bkb = ks*2 + ((lane >> 3) & 1);
            uint32_t ah[2][4], al[2][4], bh[4][4], bl[4][4];
#pragma unroll
            for (int mi = 0; mi < 2; mi++) {
                ldsm4(ah[mi], swz(tAh, arow + mi*16, akb));
                ldsm4(al[mi], swz(tAl, arow + mi*16, akb));
            }
#pragma unroll
            for (int nj = 0; nj < 4; nj++) {
                ldsm4(bh[nj], swz(tBh, brow + nj*16, bkb));
                ldsm4(bl[nj], swz(tBl, brow + nj*16, bkb));
            }
#pragma unroll
            for (int mi = 0; mi < 2; mi++)
#pragma unroll
                for (int nj = 0; nj < 4; nj++) {
                    mma16816(acc[mi][2*nj],   ah[mi], &bh[nj][0]);
                    mma16816(acc[mi][2*nj+1], ah[mi], &bh[nj][2]);
                    mma16816(acc[mi][2*nj],   ah[mi], &bl[nj][0]);
                    mma16816(acc[mi][2*nj+1], ah[mi], &bl[nj][2]);
                    mma16816(acc[mi][2*nj],   al[mi], &bh[nj][0]);
                    mma16816(acc[mi][2*nj+1], al[mi], &bh[nj][2]);
                }
        }
        __syncthreads();
    }

    // epilogue straight from register fragments
#pragma unroll
    for (int mi = 0; mi < 2; mi++) {
        const int r0 = m0 + wm + mi*16 + (lane >> 2);
#pragma unroll
        for (int nb = 0; nb < 8; nb++) {
            const int c = n0 + wn + nb*8 + (lane & 3)*2;
            if (c < N) {
                const float* a = acc[mi][nb];
                const long long off0 = coff + (long long)r0 * ldc + c;
                const long long off1 = off0 + 8LL * ldc;
                if (mode == 0) {
                    *(float2*)(C + off0) = make_float2(a[0], a[1]);
                    *(float2*)(C + off1) = make_float2(a[2], a[3]);
                } else {
                    bf16 h0,l0,h1,l1;
                    split2(a[0],h0,l0); split2(a[1],h1,l1);
                    *(__nv_bfloat162*)(Chi+off0) = __halves2bfloat162(h0,h1);
                    *(__nv_bfloat162*)(Clo+off0) = __halves2bfloat162(l0,l1);
                    split2(a[2],h0,l0); split2(a[3],h1,l1);
                    *(__nv_bfloat162*)(Chi+off1) = __halves2bfloat162(h0,h1);
                    *(__nv_bfloat162*)(Clo+off1) = __halves2bfloat162(l0,l1);
                }
            }
        }
    }
}

// ---- prep kernels ----
__global__ void split_copy(const float* __restrict__ s, bf16* __restrict__ h,
                           bf16* __restrict__ l, long long n)
{
    long long i = (long long)blockIdx.x*256 + threadIdx.x;
    if (i < n) { bf16 a, b; split2(s[i], a, b); h[i] = a; l[i] = b; }
}

// fp32 src [b][R][C] -> split bf16 dst [b][C][R]
__global__ void split_transpose(const float* __restrict__ src, bf16* __restrict__ hi,
                                bf16* __restrict__ lo, int R, int C,
                                long long sIn, long long sOut)
{
    __shared__ float t[32][33];
    int b = blockIdx.z, c0 = blockIdx.x*32, r0 = blockIdx.y*32;
    int tx = threadIdx.x, ty = threadIdx.y;
    const float* s = src + (long long)b*sIn;
#pragma unroll
    for (int j = 0; j < 4; j++)
        t[ty + j*8][tx] = s[(long long)(r0 + ty + j*8)*C + c0 + tx];
    __syncthreads();
#pragma unroll
    for (int j = 0; j < 4; j++) {
        long long o = (long long)b*sOut + (long long)(c0 + ty + j*8)*R + r0 + tx;
        bf16 h, l; split2(t[tx][ty + j*8], h, l);
        hi[o] = h; lo[o] = l;
    }
}

// bf16 src [b][R][ld_in] -> dst [b][C][R]
__global__ void transpose_bf16(const bf16* __restrict__ src, bf16* __restrict__ dst,
                               int R, int C, int ld_in, long long sIn, long long sOut)
{
    __shared__ bf16 t[32][33];
    int b = blockIdx.z, c0 = blockIdx.x*32, r0 = blockIdx.y*32;
    int tx = threadIdx.x, ty = threadIdx.y;
    const bf16* s = src + (long long)b*sIn;
#pragma unroll
    for (int j = 0; j < 4; j++)
        t[ty + j*8][tx] = s[(long long)(r0 + ty + j*8)*ld_in + c0 + tx];
    __syncthreads();
#pragma unroll
    for (int j = 0; j < 4; j++)
        dst[(long long)b*sOut + (long long)(c0 + ty + j*8)*R + r0 + tx] = t[tx][ty + j*8];
}

__global__ void rope_q_kernel(const float* __restrict__ cqr, const float* __restrict__ fc,
                              const float* __restrict__ fs, bf16* __restrict__ QCh,
                              bf16* __restrict__ QCl)
{
    int idx = blockIdx.x*256 + threadIdx.x;
    if (idx >= BATCH*SEQ*NHEAD*32) return;
    int j = idx & 31, h = (idx >> 5) & 15, bt = idx >> 9;
    int t = bt & (SEQ-1), b = bt >> 10;
    long long src = (long long)bt*(NHEAD*DHR) + h*DHR + 2*j;
    float re = cqr[src], im = cqr[src+1];
    float c = fc[t*32 + j], s = fs[t*32 + j];
    long long row = ((long long)(b*NHEAD + h)*SEQ + t)*QKDIM + NLKV + 2*j;
    bf16 h0,l0,h1,l1;
    split2(re*c - im*s, h0, l0); split2(re*s + im*c, h1, l1);
    QCh[row] = h0; QCl[row] = l0; QCh[row+1] = h1; QCl[row+1] = l1;
}

__global__ void rope_k_kernel(const float* __restrict__ ckr, const float* __restrict__ fc,
                              const float* __restrict__ fs, bf16* __restrict__ KCh,
                              bf16* __restrict__ KCl)
{
    int idx = blockIdx.x*256 + threadIdx.x;
    if (idx >= BATCH*SEQ*32) return;
    int j = idx & 31, bt = idx >> 5, t = bt & (SEQ-1);
    long long src = (long long)bt*DHR + 2*j;
    float re = ckr[src], im = ckr[src+1];
    float c = fc[t*32 + j], s = fs[t*32 + j];
    long long row = (long long)bt*QKDIM + NLKV + 2*j;
    bf16 h0,l0,h1,l1;
    split2(re*c - im*s, h0, l0); split2(re*s + im*c, h1, l1);
    KCh[row] = h0; KCl[row] = l0; KCh[row+1] = h1; KCl[row+1] = l1;
}

__global__ __launch_bounds__(256)
void softmax_split(const float* __restrict__ S, bf16* __restrict__ Phi, bf16* __restrict__ Plo)
{
    const float scale = 0.07216878364870322f;  // 1/sqrt(192)
    long long r = blockIdx.x;
    int t = (int)(r & (SEQ-1));
    const float* row = S + r*SEQ;
    bf16* ph = Phi + r*SEQ; bf16* pl = Plo + r*SEQ;
    int tid = threadIdx.x;
    __shared__ float red[256];
    float v[4], m = -1e30f;
#pragma unroll
    for (int j = 0; j < 4; j++) {
        int i = tid + j*256;
        v[j] = (i <= t) ? row[i] : -1e30f;
        m = fmaxf(m, v[j]);
    }
    red[tid] = m; __syncthreads();
    for (int s = 128; s > 0; s >>= 1) { if (tid < s) red[tid] = fmaxf(red[tid], red[tid+s]); __syncthreads(); }
    m = red[0]*scale; __syncthreads();
    float sum = 0.f;
#pragma unroll
    for (int j = 0; j < 4; j++) {
        int i = tid + j*256;
        float e = (i <= t) ? __expf(v[j]*scale - m) : 0.f;
        v[j] = e; sum += e;
    }
    red[tid] = sum; __syncthreads();
    for (int s = 128; s > 0; s >>= 1) { if (tid < s) red[tid] += red[tid+s]; __syncthreads(); }
    float inv = 1.0f / red[0]; __syncthreads();
#pragma unroll
    for (int j = 0; j < 4; j++) {
        int i = tid + j*256;
        bf16 h, l; split2(v[j]*inv, h, l);
        ph[i] = h; pl[i] = l;
    }
}

// ---- launch ----
extern "C" void kernel_launch(void* const* d_in, const int* in_sizes, int n_in,
                              void* d_out, int out_size)
{
    const float* x     = (const float*)d_in[0];
    const float* W_dq  = (const float*)d_in[1];
    const float* W_uq  = (const float*)d_in[2];
    const float* W_dkv = (const float*)d_in[3];
    const float* W_uk  = (const float*)d_in[4];
    const float* W_uv  = (const float*)d_in[5];
    const float* W_o   = (const float*)d_in[6];
    const float* W_qr  = (const float*)d_in[7];
    const float* W_kr  = (const float*)d_in[8];
    const float* fc    = (const float*)d_in[9];
    const float* fs    = (const float*)d_in[10];
    float* out = (float*)d_out;

    cudaFuncSetAttribute(gemm3, cudaFuncAttributeMaxDynamicSharedMemorySize, SMEM_GEMM);

#define SYM(v, s) cudaGetSymbolAddress((void**)&v, s)
    bf16 *xh,*xl,*dqh,*dql,*dkvh,*dkvl,*krh,*krl,*qrh,*qrl,*uqh,*uql,*woh,*wol;
    bf16 *uvTh,*uvTl,*ukTh,*ukTl,*Zh,*Zl,*keh,*kel,*cqh,*cql,*KCh,*KCl,*QCh,*QCl;
    bf16 *Ph,*Pl,*Oh,*Ol,*cvTh,*cvTl;
    float *cqr,*ckr,*S;
    SYM(xh,g_x_h); SYM(xl,g_x_l); SYM(dqh,g_Wdq_h); SYM(dql,g_Wdq_l);
    SYM(dkvh,g_Wdkv_h); SYM(dkvl,g_Wdkv_l); SYM(krh,g_Wkr_h); SYM(krl,g_Wkr_l);
    SYM(qrh,g_Wqr_h); SYM(qrl,g_Wqr_l); SYM(uqh,g_Wuq_h); SYM(uql,g_Wuq_l);
    SYM(woh,g_Wo_h); SYM(wol,g_Wo_l); SYM(uvTh,g_WuvT_h); SYM(uvTl,g_WuvT_l);
    SYM(ukTh,g_WukT_h); SYM(ukTl,g_WukT_l); SYM(Zh,g_Z_h); SYM(Zl,g_Z_l);
    SYM(keh,g_keffT_h); SYM(kel,g_keffT_l); SYM(cqh,g_cq_h); SYM(cql,g_cq_l);
    SYM(KCh,g_KC_h); SYM(KCl,g_KC_l); SYM(QCh,g_QC_h); SYM(QCl,g_QC_l);
    SYM(Ph,g_P_h); SYM(Pl,g_P_l); SYM(Oh,g_O_h); SYM(Ol,g_O_l);
    SYM(cvTh,g_ckvT_h); SYM(cvTl,g_ckvT_l);
    SYM(cqr,g_cqr); SYM(ckr,g_ckr); SYM(S,g_S);
#undef SYM

    auto SC = [](const float* s, bf16* h, bf16* l, long long n) {
        split_copy<<<(unsigned)((n + 255)/256), 256>>>(s, h, l, n);
    };
    SC(x, xh, xl, 8388608);
    SC(W_dq, dqh, dql, 1048576);
    SC(W_dkv, dkvh, dkvl, 1048576);
    SC(W_kr, krh, krl, 131072);
    SC(W_qr, qrh, qrl, 524288);
    SC(W_uq, uqh, uql, 1048576);
    SC(W_o, woh, wol, 4194304);
    // W_uv (2048x512) -> WuvT (512x2048); W_uk per head (128x512) -> WukT (512x128)
    split_transpose<<<dim3(16, 64, 1), dim3(32, 8)>>>(W_uv, uvTh, uvTl, 2048, 512, 0, 0);
    split_transpose<<<dim3(16, 4, 16), dim3(32, 8)>>>(W_uk, ukTh, ukTl, 128, 512, 65536, 65536);

    dim3 blk(256);
    // 1. Z = W_o @ W_uv  (2048x512, K=2048) -> split
    gemm3<<<dim3(4, 16, 1), blk, SMEM_GEMM>>>(woh, wol, 0, 0, 2048, uvTh, uvTl, 0, 0, 2048,
        nullptr, Zh, Zl, 0, 0, 512, 2048, 512, 2048, 1, 1, 0);
    // 2. keffT[h] = WukT_h @ Wuq_h^T  (512x512, K=128) -> split
    gemm3<<<dim3(4, 4, 16), blk, SMEM_GEMM>>>(ukTh, ukTl, 0, 65536, 128, uqh, uql, 0, 128, 2048,
        nullptr, keh, kel, 0, 262144, 512, 512, 512, 128, 16, 1, 0);
    // 3. c_q = x @ W_dq^T (4096x512, K=2048) -> split
    gemm3<<<dim3(4, 32, 1), blk, SMEM_GEMM>>>(xh, xl, 0, 0, 2048, dqh, dql, 0, 0, 2048,
        nullptr, cqh, cql, 0, 0, 512, 4096, 512, 2048, 1, 1, 0);
    // 4. c_kv -> KC[:, 0:512] split (ldc=576)
    gemm3<<<dim3(4, 32, 1), blk, SMEM_GEMM>>>(xh, xl, 0, 0, 2048, dkvh, dkvl, 0, 0, 2048,
        nullptr, KCh, KCl, 0, 0, QKDIM, 4096, 512, 2048, 1, 1, 0);
    // 5. c_kr = x @ W_kr^T (4096x64) -> fp32
    gemm3<<<dim3(1, 32, 1), blk, SMEM_GEMM>>>(xh, xl, 0, 0, 2048, krh, krl, 0, 0, 2048,
        ckr, nullptr, nullptr, 0, 0, 64, 4096, 64, 2048, 1, 0, 0);
    // 6. c_qr = c_q @ W_qr^T (4096x1024, K=512) -> fp32
    gemm3<<<dim3(8, 32, 1), blk, SMEM_GEMM>>>(cqh, cql, 0, 0, 512, qrh, qrl, 0, 0, 512,
        cqr, nullptr, nullptr, 0, 0, 1024, 4096, 1024, 512, 1, 0, 0);
    // 7. RoPE tails
    rope_q_kernel<<<(BATCH*SEQ*NHEAD*32 + 255)/256, 256>>>(cqr, fc, fs, QCh, QCl);
    rope_k_kernel<<<(BATCH*SEQ*32 + 255)/256, 256>>>(ckr, fc, fs, KCh, KCl);
    // 8. q_abs[b,h] = c_q[b] @ keffT[h]^T -> QC[:, 0:512] split (ldc=576)
    gemm3<<<dim3(4, 8, 64), blk, SMEM_GEMM>>>(cqh, cql, 524288, 0, 512, keh, kel, 0, 262144, 512,
        nullptr, QCh, QCl, 9437184, 589824, QKDIM, 1024, 512, 512, 16, 1, 0);
    // 9. S[b,h] = QC[b,h] @ KC[b]^T (1024x1024, K=576), causal skip -> fp32
    gemm3<<<dim3(8, 8, 64), blk, SMEM_GEMM>>>(QCh, QCl, 9437184, 589824, QKDIM,
        KCh, KCl, 589824, 0, QKDIM,
        S, nullptr, nullptr, 16777216, 1048576, 1024, 1024, 1024, 576, 16, 0, 1);
    // 10. softmax -> split P
    softmax_split<<<BATCH*NHEAD*SEQ, 256>>>(S, Ph, Pl);
    // ckvT[b] = transpose(KC[b][:, 0:512]) (512x1024)
    transpose_bf16<<<dim3(16, 32, 4), dim3(32, 8)>>>(KCh, cvTh, 1024, 512, QKDIM, 589824, 524288);
    transpose_bf16<<<dim3(16, 32, 4), dim3(32, 8)>>>(KCl, cvTl, 1024, 512, QKDIM, 589824, 524288);
    // 11. O[b,h] = P[b,h] @ ckvT[b]^T (1024x512, K clipped) -> split
    gemm3<<<dim3(4, 8, 64), blk, SMEM_GEMM>>>(Ph, Pl, 16777216, 1048576, 1024,
        cvTh, cvTl, 524288, 0, 1024,
        nullptr, Oh, Ol, 8388608, 524288, 512, 1024, 512, 1024, 16, 1, 2);
    // 12. out[b][:, h*128:+128] = O[b,h] @ Z_h^T (1024x128, K=512) -> fp32
    gemm3<<<dim3(1, 8, 64), blk, SMEM_GEMM>>>(Oh, Ol, 8388608, 524288, 512,
        Zh, Zl, 0, 65536, 512,
        out, nullptr, nullptr, 2097152, 128, 2048, 1024, 128, 512, 16, 0, 0);
}

// round 5
// speedup vs baseline: 6.9404x; 1.1567x over previous
#include <cuda_runtime.h>
#include <cuda_bf16.h>
#include <stdint.h>
#include <math.h>

using bf16 = __nv_bfloat16;

constexpr int BATCH = 4, SEQ = 1024, CDIM = 2048, NHEAD = 16, HS = 128;
constexpr int NLQ = 512, NLKV = 512, DHR = 64, QKDIM = 576;

// ---- scratch (hi/lo bf16 split pairs) ----
__device__ __align__(128) bf16 g_x_h[8388608],   g_x_l[8388608];
__device__ __align__(128) bf16 g_Wdq_h[1048576], g_Wdq_l[1048576];
__device__ __align__(128) bf16 g_Wdkv_h[1048576],g_Wdkv_l[1048576];
__device__ __align__(128) bf16 g_Wkr_h[131072],  g_Wkr_l[131072];
__device__ __align__(128) bf16 g_Wqr_h[524288],  g_Wqr_l[524288];
__device__ __align__(128) bf16 g_Wuq_h[1048576], g_Wuq_l[1048576];
__device__ __align__(128) bf16 g_Wo_h[4194304],  g_Wo_l[4194304];
__device__ __align__(128) bf16 g_WuvT_h[1048576],g_WuvT_l[1048576];
__device__ __align__(128) bf16 g_WukT_h[1048576],g_WukT_l[1048576];
__device__ __align__(128) bf16 g_Z_h[1048576],   g_Z_l[1048576];
__device__ __align__(128) bf16 g_keffT_h[4194304],g_keffT_l[4194304];
__device__ __align__(128) bf16 g_cq_h[2097152],  g_cq_l[2097152];
__device__ __align__(128) bf16 g_KC_h[2359296],  g_KC_l[2359296];
__device__ __align__(128) bf16 g_QC_h[37748736], g_QC_l[37748736];
__device__ __align__(128) bf16 g_P_h[67108864],  g_P_l[67108864];
__device__ __align__(128) bf16 g_vT_h[8388608],  g_vT_l[8388608];   // [b,h] 128x1024
__device__ __align__(128) float g_cqr[4194304], g_ckr[262144], g_S[67108864];

// ---- helpers ----
__device__ __forceinline__ void split2(float v, bf16& h, bf16& l) {
    h = __float2bfloat16(v);
    l = __float2bfloat16(v - __bfloat162float(h));
}
__device__ __forceinline__ void ldsm4(uint32_t* r, uint32_t addr) {
    asm volatile("ldmatrix.sync.aligned.m8n8.x4.shared.b16 {%0,%1,%2,%3}, [%4];"
        : "=r"(r[0]), "=r"(r[1]), "=r"(r[2]), "=r"(r[3]) : "r"(addr));
}
__device__ __forceinline__ void mma16816(float* d, const uint32_t* a, const uint32_t* b) {
    asm volatile("mma.sync.aligned.m16n8k16.row.col.f32.bf16.bf16.f32 "
        "{%0,%1,%2,%3}, {%4,%5,%6,%7}, {%8,%9}, {%0,%1,%2,%3};"
        : "+f"(d[0]), "+f"(d[1]), "+f"(d[2]), "+f"(d[3])
        : "r"(a[0]), "r"(a[1]), "r"(a[2]), "r"(a[3]), "r"(b[0]), "r"(b[1]));
}
__device__ __forceinline__ uint32_t swz(uint32_t tile_base, int r, int kb16) {
    uint32_t byte = (uint32_t)(r * 128 + kb16 * 16);
    return tile_base + (byte ^ ((byte >> 3) & 0x70));
}

// ---- HMMA batched GEMM: D = (Ah+Al) @ (Bh+Bl)^T (3-term split) ----
// A: MxK (lda), B: NxK (ldb), K-contiguous. Batch z: z0=z/zdiv, z1=z%zdiv.
// mode 0: fp32 C; mode 1: split Chi/Clo. causal 1: skip masked tiles; 2: clip K.
constexpr int BM = 128, BN = 128, BKC = 64;
constexpr int TILE_B = 16384;                 // one 128x64 bf16 tile
constexpr int BUF_B  = 4 * TILE_B;            // Ah, Al, Bh, Bl
constexpr int NSTAGE = 3;
constexpr int SMEM_GEMM = NSTAGE * BUF_B;     // 192 KB

__global__ __launch_bounds__(256, 1)
void gemm3(const bf16* __restrict__ Ah, const bf16* __restrict__ Al,
           long long sA0, long long sA1, int lda,
           const bf16* __restrict__ Bh, const bf16* __restrict__ Bl,
           long long sB0, long long sB1, int ldb,
           float* __restrict__ C, bf16* __restrict__ Chi, bf16* __restrict__ Clo,
           long long sC0, long long sC1, int ldc,
           int M, int N, int K, int zdiv, int mode, int causal)
{
    const int m0 = blockIdx.y * BM, n0 = blockIdx.x * BN;
    if (causal == 1 && n0 >= m0 + BM) return;
    const int z = blockIdx.z, z0 = z / zdiv, z1 = z % zdiv;
    Ah += z0*sA0 + z1*sA1;  Al += z0*sA0 + z1*sA1;
    Bh += z0*sB0 + z1*sB1;  Bl += z0*sB0 + z1*sB1;
    const long long coff = z0*sC0 + z1*sC1;

    extern __shared__ __align__(1024) char smem[];
    const uint32_t sb = (uint32_t)__cvta_generic_to_shared(smem);
    const int tid = threadIdx.x, wid = tid >> 5, lane = tid & 31;
    const int wm = (wid & 3) * 32;      // warp m-offset
    const int wn = (wid >> 2) * 64;     // warp n-offset

    const int Keff = (causal == 2) ? min(K, m0 + BM) : K;
    const int nch = Keff / BKC;

    auto fill = [&](int buf, int k0) {
        const uint32_t bb = sb + buf * BUF_B;
#pragma unroll
        for (int it = 0; it < 16; it++) {
            int idx = tid + it * 256;
            int tile = idx >> 10, r = (idx >> 3) & 127, c16 = idx & 7;
            uint32_t byte = (uint32_t)(r*128 + c16*16);
            uint32_t dst = bb + tile*TILE_B + (byte ^ ((byte >> 3) & 0x70));
            if (tile < 2) {
                const bf16* src = (tile == 0 ? Ah : Al) + (long long)(m0 + r)*lda + k0 + c16*8;
                asm volatile("cp.async.cg.shared.global [%0], [%1], 16;"::"r"(dst),"l"(src):"memory");
            } else if (n0 + r < N) {
                const bf16* src = (tile == 2 ? Bh : Bl) + (long long)(n0 + r)*ldb + k0 + c16*8;
                asm volatile("cp.async.cg.shared.global [%0], [%1], 16;"::"r"(dst),"l"(src):"memory");
            } else {
                asm volatile("st.shared.v4.b32 [%0], {%1,%1,%1,%1};"::"r"(dst),"r"(0u):"memory");
            }
        }
        asm volatile("cp.async.commit_group;" ::: "memory");
    };

    float acc[2][8][4];
#pragma unroll
    for (int i = 0; i < 2; i++)
#pragma unroll
        for (int j = 0; j < 8; j++)
#pragma unroll
            for (int q = 0; q < 4; q++) acc[i][j][q] = 0.f;

    // prefetch 2 stages
    fill(0, 0);
    if (nch > 1) fill(1, BKC);

    for (int ci = 0; ci < nch; ci++) {
        if (ci + 2 < nch) {
            fill((ci + 2) % NSTAGE, (ci + 2) * BKC);
            asm volatile("cp.async.wait_group 2;" ::: "memory");
        } else if (ci + 1 < nch) {
            asm volatile("cp.async.wait_group 1;" ::: "memory");
        } else {
            asm volatile("cp.async.wait_group 0;" ::: "memory");
        }
        __syncthreads();

        const uint32_t bb = sb + (ci % NSTAGE) * BUF_B;
        const uint32_t tAh = bb, tAl = bb + TILE_B, tBh = bb + 2*TILE_B, tBl = bb + 3*TILE_B;
        const int arow = wm + (lane & 15);
        const int brow = wn + (lane & 7) + ((lane >> 4) << 3);

#pragma unroll
        for (int ks = 0; ks < 4; ks++) {
            const int akb = ks*2 + (lane >> 4);
            const int bkb = ks*2 + ((lane >> 3) & 1);
            uint32_t ah[2][4], al[2][4], bh[4][4], bl[4][4];
#pragma unroll
            for (int mi = 0; mi < 2; mi++) {
                ldsm4(ah[mi], swz(tAh, arow + mi*16, akb));
                ldsm4(al[mi], swz(tAl, arow + mi*16, akb));
            }
#pragma unroll
            for (int nj = 0; nj < 4; nj++) {
                ldsm4(bh[nj], swz(tBh, brow + nj*16, bkb));
                ldsm4(bl[nj], swz(tBl, brow + nj*16, bkb));
            }
#pragma unroll
            for (int mi = 0; mi < 2; mi++)
#pragma unroll
                for (int nj = 0; nj < 4; nj++) {
                    mma16816(acc[mi][2*nj],   ah[mi], &bh[nj][0]);
                    mma16816(acc[mi][2*nj+1], ah[mi], &bh[nj][2]);
                    mma16816(acc[mi][2*nj],   ah[mi], &bl[nj][0]);
                    mma16816(acc[mi][2*nj+1], ah[mi], &bl[nj][2]);
                    mma16816(acc[mi][2*nj],   al[mi], &bh[nj][0]);
                    mma16816(acc[mi][2*nj+1], al[mi], &bh[nj][2]);
                }
        }
        __syncthreads();
    }

    // epilogue straight from register fragments
#pragma unroll
    for (int mi = 0; mi < 2; mi++) {
        const int r0 = m0 + wm + mi*16 + (lane >> 2);
#pragma unroll
        for (int nb = 0; nb < 8; nb++) {
            const int c = n0 + wn + nb*8 + (lane & 3)*2;
            if (c < N) {
                const float* a = acc[mi][nb];
                const long long off0 = coff + (long long)r0 * ldc + c;
                const long long off1 = off0 + 8LL * ldc;
                if (mode == 0) {
                    *(float2*)(C + off0) = make_float2(a[0], a[1]);
                    *(float2*)(C + off1) = make_float2(a[2], a[3]);
                } else {
                    bf16 h0,l0,h1,l1;
                    split2(a[0],h0,l0); split2(a[1],h1,l1);
                    *(__nv_bfloat162*)(Chi+off0) = __halves2bfloat162(h0,h1);
                    *(__nv_bfloat162*)(Clo+off0) = __halves2bfloat162(l0,l1);
                    split2(a[2],h0,l0); split2(a[3],h1,l1);
                    *(__nv_bfloat162*)(Chi+off1) = __halves2bfloat162(h0,h1);
                    *(__nv_bfloat162*)(Clo+off1) = __halves2bfloat162(l0,l1);
                }
            }
        }
    }
}

// ---- prep kernels ----
__global__ void split_copy(const float* __restrict__ s, bf16* __restrict__ h,
                           bf16* __restrict__ l, long long n)
{
    long long i = (long long)blockIdx.x*256 + threadIdx.x;
    if (i < n) { bf16 a, b; split2(s[i], a, b); h[i] = a; l[i] = b; }
}

// fp32 src [b][R][C] -> split bf16 dst [b][C][R]
__global__ void split_transpose(const float* __restrict__ src, bf16* __restrict__ hi,
                                bf16* __restrict__ lo, int R, int C,
                                long long sIn, long long sOut)
{
    __shared__ float t[32][33];
    int b = blockIdx.z, c0 = blockIdx.x*32, r0 = blockIdx.y*32;
    int tx = threadIdx.x, ty = threadIdx.y;
    const float* s = src + (long long)b*sIn;
#pragma unroll
    for (int j = 0; j < 4; j++)
        t[ty + j*8][tx] = s[(long long)(r0 + ty + j*8)*C + c0 + tx];
    __syncthreads();
#pragma unroll
    for (int j = 0; j < 4; j++) {
        long long o = (long long)b*sOut + (long long)(c0 + ty + j*8)*R + r0 + tx;
        bf16 h, l; split2(t[tx][ty + j*8], h, l);
        hi[o] = h; lo[o] = l;
    }
}

__global__ void rope_q_kernel(const float* __restrict__ cqr, const float* __restrict__ fc,
                              const float* __restrict__ fs, bf16* __restrict__ QCh,
                              bf16* __restrict__ QCl)
{
    int idx = blockIdx.x*256 + threadIdx.x;
    if (idx >= BATCH*SEQ*NHEAD*32) return;
    int j = idx & 31, h = (idx >> 5) & 15, bt = idx >> 9;
    int t = bt & (SEQ-1), b = bt >> 10;
    long long src = (long long)bt*(NHEAD*DHR) + h*DHR + 2*j;
    float re = cqr[src], im = cqr[src+1];
    float c = fc[t*32 + j], s = fs[t*32 + j];
    long long row = ((long long)(b*NHEAD + h)*SEQ + t)*QKDIM + NLKV + 2*j;
    bf16 h0,l0,h1,l1;
    split2(re*c - im*s, h0, l0); split2(re*s + im*c, h1, l1);
    QCh[row] = h0; QCl[row] = l0; QCh[row+1] = h1; QCl[row+1] = l1;
}

__global__ void rope_k_kernel(const float* __restrict__ ckr, const float* __restrict__ fc,
                              const float* __restrict__ fs, bf16* __restrict__ KCh,
                              bf16* __restrict__ KCl)
{
    int idx = blockIdx.x*256 + threadIdx.x;
    if (idx >= BATCH*SEQ*32) return;
    int j = idx & 31, bt = idx >> 5, t = bt & (SEQ-1);
    long long src = (long long)bt*DHR + 2*j;
    float re = ckr[src], im = ckr[src+1];
    float c = fc[t*32 + j], s = fs[t*32 + j];
    long long row = (long long)bt*QKDIM + NLKV + 2*j;
    bf16 h0,l0,h1,l1;
    split2(re*c - im*s, h0, l0); split2(re*s + im*c, h1, l1);
    KCh[row] = h0; KCl[row] = l0; KCh[row+1] = h1; KCl[row+1] = l1;
}

__global__ __launch_bounds__(256)
void softmax_split(const float* __restrict__ S, bf16* __restrict__ Phi, bf16* __restrict__ Plo)
{
    const float scale = 0.07216878364870322f;  // 1/sqrt(192)
    long long r = blockIdx.x;
    int t = (int)(r & (SEQ-1));
    const float* row = S + r*SEQ;
    bf16* ph = Phi + r*SEQ; bf16* pl = Plo + r*SEQ;
    int tid = threadIdx.x;
    __shared__ float red[256];
    float v[4], m = -1e30f;
#pragma unroll
    for (int j = 0; j < 4; j++) {
        int i = tid + j*256;
        v[j] = (i <= t) ? row[i] : -1e30f;
        m = fmaxf(m, v[j]);
    }
    red[tid] = m; __syncthreads();
    for (int s = 128; s > 0; s >>= 1) { if (tid < s) red[tid] = fmaxf(red[tid], red[tid+s]); __syncthreads(); }
    m = red[0]*scale; __syncthreads();
    float sum = 0.f;
#pragma unroll
    for (int j = 0; j < 4; j++) {
        int i = tid + j*256;
        float e = (i <= t) ? __expf(v[j]*scale - m) : 0.f;
        v[j] = e; sum += e;
    }
    red[tid] = sum; __syncthreads();
    for (int s = 128; s > 0; s >>= 1) { if (tid < s) red[tid] += red[tid+s]; __syncthreads(); }
    float inv = 1.0f / red[0]; __syncthreads();
#pragma unroll
    for (int j = 0; j < 4; j++) {
        int i = tid + j*256;
        bf16 h, l; split2(v[j]*inv, h, l);
        ph[i] = h; pl[i] = l;
    }
}

// ---- launch ----
extern "C" void kernel_launch(void* const* d_in, const int* in_sizes, int n_in,
                              void* d_out, int out_size)
{
    const float* x     = (const float*)d_in[0];
    const float* W_dq  = (const float*)d_in[1];
    const float* W_uq  = (const float*)d_in[2];
    const float* W_dkv = (const float*)d_in[3];
    const float* W_uk  = (const float*)d_in[4];
    const float* W_uv  = (const float*)d_in[5];
    const float* W_o   = (const float*)d_in[6];
    const float* W_qr  = (const float*)d_in[7];
    const float* W_kr  = (const float*)d_in[8];
    const float* fc    = (const float*)d_in[9];
    const float* fs    = (const float*)d_in[10];
    float* out = (float*)d_out;

    cudaFuncSetAttribute(gemm3, cudaFuncAttributeMaxDynamicSharedMemorySize, SMEM_GEMM);

#define SYM(v, s) cudaGetSymbolAddress((void**)&v, s)
    bf16 *xh,*xl,*dqh,*dql,*dkvh,*dkvl,*krh,*krl,*qrh,*qrl,*uqh,*uql,*woh,*wol;
    bf16 *uvTh,*uvTl,*ukTh,*ukTl,*Zh,*Zl,*keh,*kel,*cqh,*cql,*KCh,*KCl,*QCh,*QCl;
    bf16 *Ph,*Pl,*vTh,*vTl;
    float *cqr,*ckr,*S;
    SYM(xh,g_x_h); SYM(xl,g_x_l); SYM(dqh,g_Wdq_h); SYM(dql,g_Wdq_l);
    SYM(dkvh,g_Wdkv_h); SYM(dkvl,g_Wdkv_l); SYM(krh,g_Wkr_h); SYM(krl,g_Wkr_l);
    SYM(qrh,g_Wqr_h); SYM(qrl,g_Wqr_l); SYM(uqh,g_Wuq_h); SYM(uql,g_Wuq_l);
    SYM(woh,g_Wo_h); SYM(wol,g_Wo_l); SYM(uvTh,g_WuvT_h); SYM(uvTl,g_WuvT_l);
    SYM(ukTh,g_WukT_h); SYM(ukTl,g_WukT_l); SYM(Zh,g_Z_h); SYM(Zl,g_Z_l);
    SYM(keh,g_keffT_h); SYM(kel,g_keffT_l); SYM(cqh,g_cq_h); SYM(cql,g_cq_l);
    SYM(KCh,g_KC_h); SYM(KCl,g_KC_l); SYM(QCh,g_QC_h); SYM(QCl,g_QC_l);
    SYM(Ph,g_P_h); SYM(Pl,g_P_l); SYM(vTh,g_vT_h); SYM(vTl,g_vT_l);
    SYM(cqr,g_cqr); SYM(ckr,g_ckr); SYM(S,g_S);
#undef SYM

    auto SC = [](const float* s, bf16* h, bf16* l, long long n) {
        split_copy<<<(unsigned)((n + 255)/256), 256>>>(s, h, l, n);
    };
    SC(x, xh, xl, 8388608);
    SC(W_dq, dqh, dql, 1048576);
    SC(W_dkv, dkvh, dkvl, 1048576);
    SC(W_kr, krh, krl, 131072);
    SC(W_qr, qrh, qrl, 524288);
    SC(W_uq, uqh, uql, 1048576);
    SC(W_o, woh, wol, 4194304);
    // W_uv (2048x512) -> WuvT (512x2048); W_uk per head (128x512) -> WukT (512x128)
    split_transpose<<<dim3(16, 64, 1), dim3(32, 8)>>>(W_uv, uvTh, uvTl, 2048, 512, 0, 0);
    split_transpose<<<dim3(16, 4, 16), dim3(32, 8)>>>(W_uk, ukTh, ukTl, 128, 512, 65536, 65536);

    dim3 blk(256);
    // 1. Z = W_o @ W_uv  (2048x512, K=2048) -> split
    gemm3<<<dim3(4, 16, 1), blk, SMEM_GEMM>>>(woh, wol, 0, 0, 2048, uvTh, uvTl, 0, 0, 2048,
        nullptr, Zh, Zl, 0, 0, 512, 2048, 512, 2048, 1, 1, 0);
    // 2. keffT[h] = WukT_h @ Wuq_h^T  (512x512, K=128) -> split
    gemm3<<<dim3(4, 4, 16), blk, SMEM_GEMM>>>(ukTh, ukTl, 0, 65536, 128, uqh, uql, 0, 128, 2048,
        nullptr, keh, kel, 0, 262144, 512, 512, 512, 128, 16, 1, 0);
    // 3. c_q = x @ W_dq^T (4096x512, K=2048) -> split
    gemm3<<<dim3(4, 32, 1), blk, SMEM_GEMM>>>(xh, xl, 0, 0, 2048, dqh, dql, 0, 0, 2048,
        nullptr, cqh, cql, 0, 0, 512, 4096, 512, 2048, 1, 1, 0);
    // 4. c_kv -> KC[:, 0:512] split (ldc=576)
    gemm3<<<dim3(4, 32, 1), blk, SMEM_GEMM>>>(xh, xl, 0, 0, 2048, dkvh, dkvl, 0, 0, 2048,
        nullptr, KCh, KCl, 0, 0, QKDIM, 4096, 512, 2048, 1, 1, 0);
    // 5. vT[b,h] = Z_h (128x512) @ c_kv[b]^T (1024x512) -> split (128x1024)
    gemm3<<<dim3(8, 1, 64), blk, SMEM_GEMM>>>(Zh, Zl, 0, 65536, 512,
        KCh, KCl, 589824, 0, QKDIM,
        nullptr, vTh, vTl, 2097152, 131072, 1024, 128, 1024, 512, 16, 1, 0);
    // 6. c_kr = x @ W_kr^T (4096x64) -> fp32
    gemm3<<<dim3(1, 32, 1), blk, SMEM_GEMM>>>(xh, xl, 0, 0, 2048, krh, krl, 0, 0, 2048,
        ckr, nullptr, nullptr, 0, 0, 64, 4096, 64, 2048, 1, 0, 0);
    // 7. c_qr = c_q @ W_qr^T (4096x1024, K=512) -> fp32
    gemm3<<<dim3(8, 32, 1), blk, SMEM_GEMM>>>(cqh, cql, 0, 0, 512, qrh, qrl, 0, 0, 512,
        cqr, nullptr, nullptr, 0, 0, 1024, 4096, 1024, 512, 1, 0, 0);
    // 8. RoPE tails
    rope_q_kernel<<<(BATCH*SEQ*NHEAD*32 + 255)/256, 256>>>(cqr, fc, fs, QCh, QCl);
    rope_k_kernel<<<(BATCH*SEQ*32 + 255)/256, 256>>>(ckr, fc, fs, KCh, KCl);
    // 9. q_abs[b,h] = c_q[b] @ keffT[h]^T -> QC[:, 0:512] split (ldc=576)
    gemm3<<<dim3(4, 8, 64), blk, SMEM_GEMM>>>(cqh, cql, 524288, 0, 512, keh, kel, 0, 262144, 512,
        nullptr, QCh, QCl, 9437184, 589824, QKDIM, 1024, 512, 512, 16, 1, 0);
    // 10. S[b,h] = QC[b,h] @ KC[b]^T (1024x1024, K=576), causal skip -> fp32
    gemm3<<<dim3(8, 8, 64), blk, SMEM_GEMM>>>(QCh, QCl, 9437184, 589824, QKDIM,
        KCh, KCl, 589824, 0, QKDIM,
        S, nullptr, nullptr, 16777216, 1048576, 1024, 1024, 1024, 576, 16, 0, 1);
    // 11. softmax -> split P
    softmax_split<<<BATCH*NHEAD*SEQ, 256>>>(S, Ph, Pl);
    // 12. out[b][:, h*128:+128] = P[b,h] @ vT[b,h]^T (1024x128, K clipped) -> fp32
    gemm3<<<dim3(1, 8, 64), blk, SMEM_GEMM>>>(Ph, Pl, 16777216, 1048576, 1024,
        vTh, vTl, 2097152, 131072, 1024,
        out, nullptr, nullptr, 2097152, 128, 2048, 1024, 128, 1024, 16, 0, 2);
}